// round 12
// baseline (speedup 1.0000x reference)
#include <cuda_runtime.h>
#include <cuda_bf16.h>
#include <cstdint>

#define DIMC 768
#define NHEAD 12
#define HDIM 64
#define NB 8
#define NS 1024
#define SCALE_F 0.125f
#define EPS_F 1e-6f

// Scratch (device globals: allocation-free rule)
__device__ float    g_q [NB * NHEAD * NS * HDIM];   // fp32, pre-scaled
__device__ float    g_vt[NB * NHEAD * HDIM * NS];   // V transposed [bh][d][n], tf32
__device__ float    g_ao[NB * NS * DIMC];           // attention out, tf32-rounded
__device__ float    g_pw[DIMC * DIMC];              // proj_w tf32-rounded
__device__ uint32_t g_xbh[NB * NS * DIMC / 2];      // x bf16-hi, k-paired
__device__ uint32_t g_xbl[NB * NS * DIMC / 2];      // x bf16-lo
__device__ uint32_t g_wbh[3 * DIMC * DIMC / 2];     // qkv_w bf16-hi
__device__ uint32_t g_wbl[3 * DIMC * DIMC / 2];     // qkv_w bf16-lo
__device__ uint32_t g_kbh[NB * NHEAD * NS * HDIM / 2];  // K bf16-hi
__device__ uint32_t g_kbl[NB * NHEAD * NS * HDIM / 2];  // K bf16-lo

// ---------------------------------------------------------------------------
// helpers
// ---------------------------------------------------------------------------
__device__ __forceinline__ uint32_t f2tf32(float x) {
    uint32_t r;
    asm("cvt.rna.tf32.f32 %0, %1;" : "=r"(r) : "f"(x));
    return r;
}
__device__ __forceinline__ uint32_t pbf(float a, float b) {
    __nv_bfloat162 t = __floats2bfloat162_rn(a, b);
    return *(uint32_t*)&t;
}
__device__ __forceinline__ float resbf(float a) {
    return a - __bfloat162float(__float2bfloat16_rn(a));
}

__device__ __forceinline__ void mma1688(float* c, uint32_t a0, uint32_t a1,
                                        uint32_t a2, uint32_t a3,
                                        uint32_t b0, uint32_t b1) {
    asm volatile(
        "mma.sync.aligned.m16n8k8.row.col.f32.tf32.tf32.f32 "
        "{%0,%1,%2,%3}, {%4,%5,%6,%7}, {%8,%9}, {%0,%1,%2,%3};"
        : "+f"(c[0]), "+f"(c[1]), "+f"(c[2]), "+f"(c[3])
        : "r"(a0), "r"(a1), "r"(a2), "r"(a3), "r"(b0), "r"(b1));
}
__device__ __forceinline__ void mmabf(float* c, const uint32_t* a,
                                      uint32_t b0, uint32_t b1) {
    asm volatile(
        "mma.sync.aligned.m16n8k16.row.col.f32.bf16.bf16.f32 "
        "{%0,%1,%2,%3}, {%4,%5,%6,%7}, {%8,%9}, {%0,%1,%2,%3};"
        : "+f"(c[0]), "+f"(c[1]), "+f"(c[2]), "+f"(c[3])
        : "r"(a[0]), "r"(a[1]), "r"(a[2]), "r"(a[3]), "r"(b0), "r"(b1));
}

__device__ __forceinline__ uint32_t smem_u32(const void* p) {
    uint32_t a;
    asm("{ .reg .u64 t; cvta.to.shared.u64 t, %1; cvt.u32.u64 %0, t; }"
        : "=r"(a) : "l"(p));
    return a;
}
__device__ __forceinline__ void cpa16(uint32_t dst, const void* src) {
    asm volatile("cp.async.cg.shared.global [%0], [%1], 16;" :: "r"(dst), "l"(src));
}
#define CPA_COMMIT() asm volatile("cp.async.commit_group;" ::: "memory")
#define CPA_WAIT1()  asm volatile("cp.async.wait_group 1;" ::: "memory")

// ---------------------------------------------------------------------------
// splits
// ---------------------------------------------------------------------------
__global__ void split_bf16(const float4* __restrict__ src,
                           uint32_t* __restrict__ dh, uint32_t* __restrict__ dl,
                           int n4)
{
    int i = blockIdx.x * 256 + threadIdx.x;
    if (i >= n4) return;
    float4 v = src[i];
    __nv_bfloat162 h01 = __floats2bfloat162_rn(v.x, v.y);
    __nv_bfloat162 h23 = __floats2bfloat162_rn(v.z, v.w);
    dh[2 * i] = *(uint32_t*)&h01;
    dh[2 * i + 1] = *(uint32_t*)&h23;
    __nv_bfloat162 l01 = __floats2bfloat162_rn(v.x - __bfloat162float(h01.x),
                                               v.y - __bfloat162float(h01.y));
    __nv_bfloat162 l23 = __floats2bfloat162_rn(v.z - __bfloat162float(h23.x),
                                               v.w - __bfloat162float(h23.y));
    dl[2 * i] = *(uint32_t*)&l01;
    dl[2 * i + 1] = *(uint32_t*)&l23;
}

__global__ void split_tf32(const float4* __restrict__ src, float4* __restrict__ dh, int n4)
{
    int i = blockIdx.x * 256 + threadIdx.x;
    if (i >= n4) return;
    float4 v = src[i];
    float4 h;
    h.x = __uint_as_float(f2tf32(v.x));
    h.y = __uint_as_float(f2tf32(v.y));
    h.z = __uint_as_float(f2tf32(v.z));
    h.w = __uint_as_float(f2tf32(v.w));
    dh[i] = h;
}

// ---------------------------------------------------------------------------
// QKV GEMM, 3xBF16: C[8192,2304] = x[8192,768] @ w[2304,768]^T
// 128x128 tile, BK=32 (2 k16 chunks), 2-stage cp.async, 2 CTAs/SM.
// Epilogue: Q fp32*scale, K bf16 hi/lo packed, V transposed tf32.
// ---------------------------------------------------------------------------
#define GKU (DIMC / 2)     // 384 u32 per row
#define QP 20              // smem pitch in u32 (bank: 4*grp+qid, conflict-free)
#define QTILE (128 * QP)   // 2560 u32 = 10240 B

__global__ __launch_bounds__(256, 2) void gemm_qkv(
    const uint32_t* __restrict__ Ah, const uint32_t* __restrict__ Al,
    const uint32_t* __restrict__ Bh, const uint32_t* __restrict__ Bl)
{
    extern __shared__ uint32_t smq[];
    const uint32_t smb = smem_u32(smq);

    const int tid = threadIdx.x;
    const int warp = tid >> 5, lane = tid & 31;
    const int warpM = warp >> 2, warpN = warp & 3;
    const int grp = lane >> 2, qid = lane & 3;
    const int brow = blockIdx.y * 128;
    const int bcol = blockIdx.x * 128;

    // 2 chunks (16B) per tile per thread
    size_t aoff[2], boff[2];
    uint32_t soff[2];
#pragma unroll
    for (int i = 0; i < 2; i++) {
        int ff = tid + 256 * i;
        int r = ff >> 2, c4 = (ff & 3) << 2;
        aoff[i] = (size_t)(brow + r) * GKU + c4;
        boff[i] = (size_t)(bcol + r) * GKU + c4;
        soff[i] = (uint32_t)(r * QP + c4) * 4u;
    }

    auto issue = [&](int s, int st) {
        const uint32_t base = smb + (uint32_t)(st * 4 * QTILE) * 4u;
        const int k0 = s * 16;
#pragma unroll
        for (int i = 0; i < 2; i++) {
            cpa16(base + 0 * QTILE * 4 + soff[i], Ah + aoff[i] + k0);
            cpa16(base + 1 * QTILE * 4 + soff[i], Bh + boff[i] + k0);
            cpa16(base + 2 * QTILE * 4 + soff[i], Al + aoff[i] + k0);
            cpa16(base + 3 * QTILE * 4 + soff[i], Bl + boff[i] + k0);
        }
        CPA_COMMIT();
    };

    float acc[4][4][4];
#pragma unroll
    for (int mf = 0; mf < 4; mf++)
#pragma unroll
        for (int nf = 0; nf < 4; nf++)
#pragma unroll
            for (int q = 0; q < 4; q++) acc[mf][nf][q] = 0.f;

    issue(0, 0);
    issue(1, 1);

#pragma unroll 1
    for (int s = 0; s < 24; s++) {
        CPA_WAIT1();
        __syncthreads();
        const uint32_t* base = smq + (s & 1) * 4 * QTILE;
        const uint32_t* AhU = base;
        const uint32_t* BhU = base + QTILE;
        const uint32_t* AlU = base + 2 * QTILE;
        const uint32_t* BlU = base + 3 * QTILE;

#pragma unroll
        for (int ck = 0; ck < 2; ck++) {
            const int ck8 = ck * 8;
            uint32_t bh0[4], bh1[4], bl0[4], bl1[4];
#pragma unroll
            for (int nf = 0; nf < 4; nf++) {
                int rb = (warpN * 32 + nf * 8 + grp) * QP + ck8 + qid;
                bh0[nf] = BhU[rb]; bh1[nf] = BhU[rb + 4];
                bl0[nf] = BlU[rb]; bl1[nf] = BlU[rb + 4];
            }
#pragma unroll
            for (int mf = 0; mf < 4; mf++) {
                int ra = (warpM * 64 + mf * 16 + grp) * QP + ck8 + qid;
                uint32_t ah[4] = {AhU[ra], AhU[ra + 8 * QP], AhU[ra + 4], AhU[ra + 8 * QP + 4]};
                uint32_t al[4] = {AlU[ra], AlU[ra + 8 * QP], AlU[ra + 4], AlU[ra + 8 * QP + 4]};
#pragma unroll
                for (int nf = 0; nf < 4; nf++) {
                    mmabf(acc[mf][nf], ah, bh0[nf], bh1[nf]);
                    mmabf(acc[mf][nf], ah, bl0[nf], bl1[nf]);
                    mmabf(acc[mf][nf], al, bh0[nf], bh1[nf]);
                }
            }
        }
        __syncthreads();
        if (s + 2 < 24) issue(s + 2, s & 1);
        else CPA_COMMIT();
    }

    // epilogue: scatter Q / K(bf16 hi-lo) / V(transposed tf32)
#pragma unroll
    for (int mf = 0; mf < 4; mf++) {
#pragma unroll
        for (int nf = 0; nf < 4; nf++) {
            int row = brow + warpM * 64 + mf * 16 + grp;
            int col = bcol + warpN * 32 + nf * 8 + qid * 2;
#pragma unroll
            for (int half = 0; half < 2; half++) {
                int r = row + half * 8;
                float c0 = acc[mf][nf][half * 2 + 0];
                float c1 = acc[mf][nf][half * 2 + 1];
                int sidx = col / DIMC;
                int rem = col - sidx * DIMC;
                int h = rem >> 6, d0 = rem & 63;
                int b = r >> 10, n = r & 1023;
                int bh = b * NHEAD + h;
                if (sidx == 0) {
                    size_t idx = ((size_t)bh * NS + n) * HDIM + d0;
                    *(float2*)&g_q[idx] = make_float2(c0 * SCALE_F, c1 * SCALE_F);
                } else if (sidx == 1) {
                    __nv_bfloat162 hv = __floats2bfloat162_rn(c0, c1);
                    __nv_bfloat162 lv = __floats2bfloat162_rn(
                        c0 - __bfloat162float(hv.x), c1 - __bfloat162float(hv.y));
                    size_t idx = ((size_t)bh * NS + n) * (HDIM / 2) + (d0 >> 1);
                    g_kbh[idx] = *(uint32_t*)&hv;
                    g_kbl[idx] = *(uint32_t*)&lv;
                } else {
                    size_t idx = ((size_t)bh * HDIM + d0) * NS + n;
                    g_vt[idx] = __uint_as_float(f2tf32(c0));
                    g_vt[idx + NS] = __uint_as_float(f2tf32(c1));
                }
            }
        }
    }
}

// ---------------------------------------------------------------------------
// proj GEMM (single tf32): out[8192,768] = g_ao @ proj_w^T + bias
// ---------------------------------------------------------------------------
#define LDA 36
#define TILEF (128 * LDA)

__global__ __launch_bounds__(256, 2) void proj_gemm(
    const float* __restrict__ Ahg, const float* __restrict__ Bhg,
    const float* __restrict__ bias, float* __restrict__ Cout)
{
    extern __shared__ float smf[];
    const uint32_t smb = smem_u32(smf);

    const int tid = threadIdx.x;
    const int warp = tid >> 5, lane = tid & 31;
    const int warpM = warp >> 2, warpN = warp & 3;
    const int grp = lane >> 2, qid = lane & 3;
    const int brow = blockIdx.y * 128;
    const int bcol = blockIdx.x * 128;

    size_t aoff[4], boff[4];
    uint32_t soff[4];
#pragma unroll
    for (int i = 0; i < 4; i++) {
        int ff = tid + 256 * i;
        int r = ff >> 3, kq = (ff & 7) << 2;
        aoff[i] = (size_t)(brow + r) * DIMC + kq;
        boff[i] = (size_t)(bcol + r) * DIMC + kq;
        soff[i] = (uint32_t)(r * LDA + kq) * 4u;
    }

    auto issue = [&](int s, int st) {
        const uint32_t base = smb + (uint32_t)(st * 2) * (TILEF * 4);
        const int k0 = s * 32;
#pragma unroll
        for (int i = 0; i < 4; i++) {
            cpa16(base + soff[i], Ahg + aoff[i] + k0);
            cpa16(base + TILEF * 4 + soff[i], Bhg + boff[i] + k0);
        }
        CPA_COMMIT();
    };

    float acc[4][4][4];
#pragma unroll
    for (int mf = 0; mf < 4; mf++)
#pragma unroll
        for (int nf = 0; nf < 4; nf++)
#pragma unroll
            for (int q = 0; q < 4; q++) acc[mf][nf][q] = 0.f;

    issue(0, 0);
    issue(1, 1);

    const int afr = (warpM * 64 + grp) * LDA + qid;
    const int bfr = (warpN * 32 + grp) * LDA + qid;

#pragma unroll 1
    for (int s = 0; s < 24; s++) {
        CPA_WAIT1();
        __syncthreads();
        const float* base = smf + (s & 1) * 2 * TILEF;
        const uint32_t* AhU = (const uint32_t*)(base + afr);
        const uint32_t* BhU = (const uint32_t*)(base + TILEF + bfr);

#pragma unroll
        for (int ks = 0; ks < 4; ks++) {
            const int ko = ks * 8;
            uint32_t bh0[4], bh1[4];
#pragma unroll
            for (int nf = 0; nf < 4; nf++) {
                bh0[nf] = BhU[nf * 8 * LDA + ko];
                bh1[nf] = BhU[nf * 8 * LDA + ko + 4];
            }
#pragma unroll
            for (int mf = 0; mf < 4; mf++) {
                const int ao = mf * 16 * LDA + ko;
                uint32_t ah0 = AhU[ao],     ah1 = AhU[ao + 8 * LDA];
                uint32_t ah2 = AhU[ao + 4], ah3 = AhU[ao + 8 * LDA + 4];
#pragma unroll
                for (int nf = 0; nf < 4; nf++)
                    mma1688(acc[mf][nf], ah0, ah1, ah2, ah3, bh0[nf], bh1[nf]);
            }
        }
        __syncthreads();
        if (s + 2 < 24) issue(s + 2, s & 1);
        else CPA_COMMIT();
    }

#pragma unroll
    for (int mf = 0; mf < 4; mf++) {
#pragma unroll
        for (int nf = 0; nf < 4; nf++) {
            int row = brow + warpM * 64 + mf * 16 + grp;
            int col = bcol + warpN * 32 + nf * 8 + qid * 2;
#pragma unroll
            for (int half = 0; half < 2; half++) {
                int r = row + half * 8;
                float2 bv = *(const float2*)&bias[col];
                *(float2*)&Cout[(size_t)r * DIMC + col] = make_float2(
                    acc[mf][nf][half * 2 + 0] + bv.x,
                    acc[mf][nf][half * 2 + 1] + bv.y);
            }
        }
    }
}

// ---------------------------------------------------------------------------
// Attention: S = Q K^T in 3xBF16 (Q frags reg-resident, K bf16 hi/lo smem),
// one-pass policy softmax (no shift), O += P V in single tf32.
// ---------------------------------------------------------------------------
#define KP 36                            // u32 pitch for K tiles
#define KTB (64 * KP * 4)                // 9216 B per K tile
#define VTB (64 * 68 * 4)                // 17408 B per V tile
#define OFF_KH 0
#define OFF_KL (2 * KTB)                 // 18432
#define OFF_VT (4 * KTB)                 // 36864
#define OFF_PS (4 * KTB + 2 * VTB)       // 71680
#define ATT_SMEM (OFF_PS + 128 * 68 * 4) // 106496 B
#define LDV 68
#define LDP 68

__global__ __launch_bounds__(256) void attn_mma(const float* __restrict__ policy)
{
    extern __shared__ char sma[];
    const uint32_t smb = smem_u32(sma);
    float* PsF = (float*)(sma + OFF_PS);

    const int tid = threadIdx.x;
    const int warp = tid >> 5, lane = tid & 31;
    const int grp = lane >> 2, qid = lane & 3;
    const int bh = blockIdx.y;
    const int b = bh / NHEAD;
    const int h = bh - b * NHEAD;
    const int row0 = blockIdx.x * 128;

    const uint32_t* kbh = g_kbh + (size_t)bh * NS * (HDIM / 2);
    const uint32_t* kbl = g_kbl + (size_t)bh * NS * (HDIM / 2);
    const float* vtg = g_vt + (size_t)bh * HDIM * NS;
    const float* Qg  = g_q + (size_t)bh * NS * HDIM;
    const float* pol = policy + b * NS;

    const int lr = tid >> 2;            // 0..63
    const int lc4 = (tid & 3) << 2;     // u32 / float col base

    auto issue = [&](int mt, int st) {
        const int m0 = mt * 64;
#pragma unroll
        for (int j = 0; j < 32; j += 16) {
            uint32_t doff = (uint32_t)(lr * KP + lc4 + j) * 4u;
            cpa16(smb + OFF_KH + st * KTB + doff, kbh + (size_t)(m0 + lr) * 32 + lc4 + j);
            cpa16(smb + OFF_KL + st * KTB + doff, kbl + (size_t)(m0 + lr) * 32 + lc4 + j);
        }
#pragma unroll
        for (int j = 0; j < 64; j += 16) {
            cpa16(smb + OFF_VT + st * VTB + (uint32_t)(lr * LDV + lc4 + j) * 4u,
                  vtg + (size_t)lr * NS + m0 + lc4 + j);
        }
        CPA_COMMIT();
    };

    issue(0, 0);
    issue(1, 1);

    // Q fragments: bf16 hi/lo, register-resident (4 k16 chunks)
    uint32_t qh[4][4], ql[4][4];
    {
        const float* Qw = Qg + (size_t)(row0 + warp * 16) * HDIM;
#pragma unroll
        for (int ck = 0; ck < 4; ck++) {
            int c0 = ck * 16 + 2 * qid;
            float x00 = Qw[grp * 64 + c0],       x01 = Qw[grp * 64 + c0 + 1];
            float x10 = Qw[(grp + 8) * 64 + c0], x11 = Qw[(grp + 8) * 64 + c0 + 1];
            float x20 = Qw[grp * 64 + c0 + 8],   x21 = Qw[grp * 64 + c0 + 9];
            float x30 = Qw[(grp + 8) * 64 + c0 + 8], x31 = Qw[(grp + 8) * 64 + c0 + 9];
            qh[ck][0] = pbf(x00, x01); ql[ck][0] = pbf(resbf(x00), resbf(x01));
            qh[ck][1] = pbf(x10, x11); ql[ck][1] = pbf(resbf(x10), resbf(x11));
            qh[ck][2] = pbf(x20, x21); ql[ck][2] = pbf(resbf(x20), resbf(x21));
            qh[ck][3] = pbf(x30, x31); ql[ck][3] = pbf(resbf(x30), resbf(x31));
        }
    }

    float accO[8][4];
#pragma unroll
    for (int nf = 0; nf < 8; nf++)
#pragma unroll
        for (int q = 0; q < 4; q++) accO[nf][q] = 0.f;
    float l0 = 0.f, l1 = 0.f;
    const int rg0 = row0 + warp * 16 + grp;
    const int rg1 = rg0 + 8;

#pragma unroll 1
    for (int mt = 0; mt < 16; mt++) {
        const int m0 = mt * 64;
        const int st = mt & 1;
        CPA_WAIT1();
        __syncthreads();

        const uint32_t* KhU = (const uint32_t*)(sma + OFF_KH + st * KTB);
        const uint32_t* KlU = (const uint32_t*)(sma + OFF_KL + st * KTB);
        const uint32_t* VtU = (const uint32_t*)(sma + OFF_VT + st * VTB);
        const uint32_t* PsU = (const uint32_t*)PsF;

        // S = Q K^T (3xBF16)
        float c[8][4];
#pragma unroll
        for (int nf = 0; nf < 8; nf++)
#pragma unroll
            for (int q = 0; q < 4; q++) c[nf][q] = 0.f;
#pragma unroll
        for (int ck = 0; ck < 4; ck++) {
#pragma unroll
            for (int nf = 0; nf < 8; nf++) {
                int rb = (nf * 8 + grp) * KP + ck * 8 + qid;
                uint32_t b0 = KhU[rb], b1 = KhU[rb + 4];
                uint32_t l0r = KlU[rb], l1r = KlU[rb + 4];
                mmabf(c[nf], qh[ck], b0, b1);
                mmabf(c[nf], qh[ck], l0r, l1r);
                mmabf(c[nf], ql[ck], b0, b1);
            }
        }

        // one-pass softmax (no shift); P truncated to tf32; l from truncated P
        float tl0 = 0.f, tl1 = 0.f;
        float* Pw0 = PsF + (warp * 16 + grp) * LDP + 2 * qid;
        float* Pw1 = Pw0 + 8 * LDP;
#pragma unroll
        for (int nf = 0; nf < 8; nf++) {
            int mg = m0 + nf * 8 + 2 * qid;
            float2 pp = *(const float2*)&pol[mg];
            float w00 = (mg == rg0) ? 1.f : pp.x;
            float w01 = (mg + 1 == rg0) ? 1.f : pp.y;
            float w10 = (mg == rg1) ? 1.f : pp.x;
            float w11 = (mg + 1 == rg1) ? 1.f : pp.y;
            float e00 = __expf(c[nf][0]) * w00;
            float e01 = __expf(c[nf][1]) * w01;
            float e10 = __expf(c[nf][2]) * w10;
            float e11 = __expf(c[nf][3]) * w11;
            float t00 = __uint_as_float(__float_as_uint(e00) & 0xFFFFE000u);
            float t01 = __uint_as_float(__float_as_uint(e01) & 0xFFFFE000u);
            float t10 = __uint_as_float(__float_as_uint(e10) & 0xFFFFE000u);
            float t11 = __uint_as_float(__float_as_uint(e11) & 0xFFFFE000u);
            tl0 += t00 + t01;
            tl1 += t10 + t11;
            *(float2*)&Pw0[nf * 8] = make_float2(t00, t01);
            *(float2*)&Pw1[nf * 8] = make_float2(t10, t11);
        }
        tl0 += __shfl_xor_sync(0xffffffffu, tl0, 1);
        tl0 += __shfl_xor_sync(0xffffffffu, tl0, 2);
        tl1 += __shfl_xor_sync(0xffffffffu, tl1, 1);
        tl1 += __shfl_xor_sync(0xffffffffu, tl1, 2);
        l0 += tl0;
        l1 += tl1;
        __syncwarp();

        // O += P V (tf32)
#pragma unroll
        for (int ks = 0; ks < 8; ks++) {
            const int ko = ks * 8;
            int pb = (warp * 16 + grp) * LDP + ko + qid;
            uint32_t a0 = PsU[pb], a1 = PsU[pb + 8 * LDP];
            uint32_t a2 = PsU[pb + 4], a3 = PsU[pb + 8 * LDP + 4];
#pragma unroll
            for (int nf = 0; nf < 8; nf++) {
                int vb = (nf * 8 + grp) * LDV + ko + qid;
                mma1688(accO[nf], a0, a1, a2, a3, VtU[vb], VtU[vb + 4]);
            }
        }
        __syncthreads();
        if (mt + 2 < 16) issue(mt + 2, st);
        else CPA_COMMIT();
    }

    // epilogue: normalize, tf32-round (proj A-stream), write g_ao
    float inv0 = 1.0f / (l0 + EPS_F);
    float inv1 = 1.0f / (l1 + EPS_F);
#pragma unroll
    for (int nf = 0; nf < 8; nf++) {
        int d = nf * 8 + 2 * qid;
        size_t b0a = ((size_t)(b * NS + rg0)) * DIMC + h * HDIM + d;
        size_t b1a = ((size_t)(b * NS + rg1)) * DIMC + h * HDIM + d;
        *(float2*)&g_ao[b0a] = make_float2(
            __uint_as_float(f2tf32(accO[nf][0] * inv0)),
            __uint_as_float(f2tf32(accO[nf][1] * inv0)));
        *(float2*)&g_ao[b1a] = make_float2(
            __uint_as_float(f2tf32(accO[nf][2] * inv1)),
            __uint_as_float(f2tf32(accO[nf][3] * inv1)));
    }
}

extern "C" void kernel_launch(void* const* d_in, const int* in_sizes, int n_in,
                              void* d_out, int out_size)
{
    const float* x      = (const float*)d_in[0];
    const float* policy = (const float*)d_in[1];
    const float* qkv_w  = (const float*)d_in[2];
    const float* proj_w = (const float*)d_in[3];
    const float* proj_b = (const float*)d_in[4];
    float* out = (float*)d_out;

    const int SMEMQ = 2 * 4 * QTILE * 4;  // 81920 B
    const int SMEMP = 2 * 2 * TILEF * 4;  // 73728 B
    static bool attr_done = false;
    if (!attr_done) {
        cudaFuncSetAttribute(gemm_qkv, cudaFuncAttributeMaxDynamicSharedMemorySize, SMEMQ);
        cudaFuncSetAttribute(proj_gemm, cudaFuncAttributeMaxDynamicSharedMemorySize, SMEMP);
        cudaFuncSetAttribute(attn_mma, cudaFuncAttributeMaxDynamicSharedMemorySize, ATT_SMEM);
        attr_done = true;
    }

    // Device addresses of ALL __device__ symbols passed as kernel args
    uint32_t *xbh, *xbl, *wbh, *wbl;
    float *pw, *ao;
    cudaGetSymbolAddress((void**)&xbh, g_xbh);
    cudaGetSymbolAddress((void**)&xbl, g_xbl);
    cudaGetSymbolAddress((void**)&wbh, g_wbh);
    cudaGetSymbolAddress((void**)&wbl, g_wbl);
    cudaGetSymbolAddress((void**)&pw, g_pw);
    cudaGetSymbolAddress((void**)&ao, g_ao);

    // 0) splits: x, qkv_w -> bf16 hi/lo packed; proj_w -> tf32-rounded
    split_bf16<<<(NB * NS * DIMC / 4 + 255) / 256, 256>>>(
        (const float4*)x, xbh, xbl, NB * NS * DIMC / 4);
    split_bf16<<<(3 * DIMC * DIMC / 4 + 255) / 256, 256>>>(
        (const float4*)qkv_w, wbh, wbl, 3 * DIMC * DIMC / 4);
    split_tf32<<<(DIMC * DIMC / 4 + 255) / 256, 256>>>(
        (const float4*)proj_w, (float4*)pw, DIMC * DIMC / 4);

    // 1) QKV (3xBF16) -> q / k(bf16 hi-lo) / v(transposed tf32)
    gemm_qkv<<<dim3(2304 / 128, 8192 / 128), 256, SMEMQ>>>(xbh, xbl, wbh, wbl);
    // 2) attention (bf16 S, tf32 PV, one-pass policy softmax)
    attn_mma<<<dim3(NS / 128, NB * NHEAD), 256, ATT_SMEM>>>(policy);
    // 3) proj (single tf32) + bias
    proj_gemm<<<dim3(DIMC / 128, 8192 / 128), 256, SMEMP>>>(ao, pw, proj_b, out);
}

// round 16
// speedup vs baseline: 1.0725x; 1.0725x over previous
#include <cuda_runtime.h>
#include <cuda_bf16.h>
#include <cstdint>

#define DIMC 768
#define NHEAD 12
#define HDIM 64
#define NB 8
#define NS 1024
#define SCALE_F 0.125f
#define EPS_F 1e-6f

// Scratch (device globals: allocation-free rule)
__device__ float    g_q [NB * NHEAD * NS * HDIM];   // fp32, pre-scaled
__device__ float    g_vt[NB * NHEAD * HDIM * NS];   // V transposed [bh][d][n], tf32
__device__ float    g_ao[NB * NS * DIMC];           // attention out, tf32-rounded
__device__ float    g_pw[DIMC * DIMC];              // proj_w tf32-rounded
__device__ uint32_t g_xbh[NB * NS * DIMC / 2];      // x bf16-hi, k-paired
__device__ uint32_t g_xbl[NB * NS * DIMC / 2];      // x bf16-lo
__device__ uint32_t g_wbh[3 * DIMC * DIMC / 2];     // qkv_w bf16-hi
__device__ uint32_t g_wbl[3 * DIMC * DIMC / 2];     // qkv_w bf16-lo
__device__ uint32_t g_kbh[NB * NHEAD * NS * HDIM / 2];  // K bf16-hi
__device__ uint32_t g_kbl[NB * NHEAD * NS * HDIM / 2];  // K bf16-lo

// ---------------------------------------------------------------------------
// helpers
// ---------------------------------------------------------------------------
__device__ __forceinline__ uint32_t f2tf32(float x) {
    uint32_t r;
    asm("cvt.rna.tf32.f32 %0, %1;" : "=r"(r) : "f"(x));
    return r;
}
__device__ __forceinline__ uint32_t pbf(float a, float b) {
    __nv_bfloat162 t = __floats2bfloat162_rn(a, b);
    return *(uint32_t*)&t;
}
__device__ __forceinline__ float resbf(float a) {
    return a - __bfloat162float(__float2bfloat16_rn(a));
}

__device__ __forceinline__ void mma1688(float* c, uint32_t a0, uint32_t a1,
                                        uint32_t a2, uint32_t a3,
                                        uint32_t b0, uint32_t b1) {
    asm volatile(
        "mma.sync.aligned.m16n8k8.row.col.f32.tf32.tf32.f32 "
        "{%0,%1,%2,%3}, {%4,%5,%6,%7}, {%8,%9}, {%0,%1,%2,%3};"
        : "+f"(c[0]), "+f"(c[1]), "+f"(c[2]), "+f"(c[3])
        : "r"(a0), "r"(a1), "r"(a2), "r"(a3), "r"(b0), "r"(b1));
}
__device__ __forceinline__ void mmabf(float* c, const uint32_t* a,
                                      uint32_t b0, uint32_t b1) {
    asm volatile(
        "mma.sync.aligned.m16n8k16.row.col.f32.bf16.bf16.f32 "
        "{%0,%1,%2,%3}, {%4,%5,%6,%7}, {%8,%9}, {%0,%1,%2,%3};"
        : "+f"(c[0]), "+f"(c[1]), "+f"(c[2]), "+f"(c[3])
        : "r"(a[0]), "r"(a[1]), "r"(a[2]), "r"(a[3]), "r"(b0), "r"(b1));
}

__device__ __forceinline__ uint32_t smem_u32(const void* p) {
    uint32_t a;
    asm("{ .reg .u64 t; cvta.to.shared.u64 t, %1; cvt.u32.u64 %0, t; }"
        : "=r"(a) : "l"(p));
    return a;
}
__device__ __forceinline__ void cpa16(uint32_t dst, const void* src) {
    asm volatile("cp.async.cg.shared.global [%0], [%1], 16;" :: "r"(dst), "l"(src));
}
#define CPA_COMMIT() asm volatile("cp.async.commit_group;" ::: "memory")
#define CPA_WAIT1()  asm volatile("cp.async.wait_group 1;" ::: "memory")

// ---------------------------------------------------------------------------
// splits
// ---------------------------------------------------------------------------
__global__ void split_bf16(const float4* __restrict__ src,
                           uint32_t* __restrict__ dh, uint32_t* __restrict__ dl,
                           int n4)
{
    int i = blockIdx.x * 256 + threadIdx.x;
    if (i >= n4) return;
    float4 v = src[i];
    __nv_bfloat162 h01 = __floats2bfloat162_rn(v.x, v.y);
    __nv_bfloat162 h23 = __floats2bfloat162_rn(v.z, v.w);
    dh[2 * i] = *(uint32_t*)&h01;
    dh[2 * i + 1] = *(uint32_t*)&h23;
    __nv_bfloat162 l01 = __floats2bfloat162_rn(v.x - __bfloat162float(h01.x),
                                               v.y - __bfloat162float(h01.y));
    __nv_bfloat162 l23 = __floats2bfloat162_rn(v.z - __bfloat162float(h23.x),
                                               v.w - __bfloat162float(h23.y));
    dl[2 * i] = *(uint32_t*)&l01;
    dl[2 * i + 1] = *(uint32_t*)&l23;
}

__global__ void split_tf32(const float4* __restrict__ src, float4* __restrict__ dh, int n4)
{
    int i = blockIdx.x * 256 + threadIdx.x;
    if (i >= n4) return;
    float4 v = src[i];
    float4 h;
    h.x = __uint_as_float(f2tf32(v.x));
    h.y = __uint_as_float(f2tf32(v.y));
    h.z = __uint_as_float(f2tf32(v.z));
    h.w = __uint_as_float(f2tf32(v.w));
    dh[i] = h;
}

// ---------------------------------------------------------------------------
// QKV GEMM, 3xBF16: C[8192,2304] = x[8192,768] @ w[2304,768]^T
// 128x128 tile, BK=32 (2 k16 chunks), 2-stage cp.async, 2 CTAs/SM.
// ---------------------------------------------------------------------------
#define GKU (DIMC / 2)     // 384 u32 per row
#define QP 20              // smem pitch in u32 (bank: 4*grp+qid, conflict-free)
#define QTILE (128 * QP)   // 2560 u32 = 10240 B

__global__ __launch_bounds__(256, 2) void gemm_qkv(
    const uint32_t* __restrict__ Ah, const uint32_t* __restrict__ Al,
    const uint32_t* __restrict__ Bh, const uint32_t* __restrict__ Bl)
{
    extern __shared__ uint32_t smq[];
    const uint32_t smb = smem_u32(smq);

    const int tid = threadIdx.x;
    const int warp = tid >> 5, lane = tid & 31;
    const int warpM = warp >> 2, warpN = warp & 3;
    const int grp = lane >> 2, qid = lane & 3;
    const int brow = blockIdx.y * 128;
    const int bcol = blockIdx.x * 128;

    size_t aoff[2], boff[2];
    uint32_t soff[2];
#pragma unroll
    for (int i = 0; i < 2; i++) {
        int ff = tid + 256 * i;
        int r = ff >> 2, c4 = (ff & 3) << 2;
        aoff[i] = (size_t)(brow + r) * GKU + c4;
        boff[i] = (size_t)(bcol + r) * GKU + c4;
        soff[i] = (uint32_t)(r * QP + c4) * 4u;
    }

    auto issue = [&](int s, int st) {
        const uint32_t base = smb + (uint32_t)(st * 4 * QTILE) * 4u;
        const int k0 = s * 16;
#pragma unroll
        for (int i = 0; i < 2; i++) {
            cpa16(base + 0 * QTILE * 4 + soff[i], Ah + aoff[i] + k0);
            cpa16(base + 1 * QTILE * 4 + soff[i], Bh + boff[i] + k0);
            cpa16(base + 2 * QTILE * 4 + soff[i], Al + aoff[i] + k0);
            cpa16(base + 3 * QTILE * 4 + soff[i], Bl + boff[i] + k0);
        }
        CPA_COMMIT();
    };

    float acc[4][4][4];
#pragma unroll
    for (int mf = 0; mf < 4; mf++)
#pragma unroll
        for (int nf = 0; nf < 4; nf++)
#pragma unroll
            for (int q = 0; q < 4; q++) acc[mf][nf][q] = 0.f;

    issue(0, 0);
    issue(1, 1);

#pragma unroll 1
    for (int s = 0; s < 24; s++) {
        CPA_WAIT1();
        __syncthreads();
        const uint32_t* base = smq + (s & 1) * 4 * QTILE;
        const uint32_t* AhU = base;
        const uint32_t* BhU = base + QTILE;
        const uint32_t* AlU = base + 2 * QTILE;
        const uint32_t* BlU = base + 3 * QTILE;

#pragma unroll
        for (int ck = 0; ck < 2; ck++) {
            const int ck8 = ck * 8;
            uint32_t bh0[4], bh1[4], bl0[4], bl1[4];
#pragma unroll
            for (int nf = 0; nf < 4; nf++) {
                int rb = (warpN * 32 + nf * 8 + grp) * QP + ck8 + qid;
                bh0[nf] = BhU[rb]; bh1[nf] = BhU[rb + 4];
                bl0[nf] = BlU[rb]; bl1[nf] = BlU[rb + 4];
            }
#pragma unroll
            for (int mf = 0; mf < 4; mf++) {
                int ra = (warpM * 64 + mf * 16 + grp) * QP + ck8 + qid;
                uint32_t ah[4] = {AhU[ra], AhU[ra + 8 * QP], AhU[ra + 4], AhU[ra + 8 * QP + 4]};
                uint32_t al[4] = {AlU[ra], AlU[ra + 8 * QP], AlU[ra + 4], AlU[ra + 8 * QP + 4]};
#pragma unroll
                for (int nf = 0; nf < 4; nf++) {
                    mmabf(acc[mf][nf], ah, bh0[nf], bh1[nf]);
                    mmabf(acc[mf][nf], ah, bl0[nf], bl1[nf]);
                    mmabf(acc[mf][nf], al, bh0[nf], bh1[nf]);
                }
            }
        }
        __syncthreads();
        if (s + 2 < 24) issue(s + 2, s & 1);
        else CPA_COMMIT();
    }

    // epilogue: scatter Q / K(bf16 hi-lo) / V(transposed tf32)
#pragma unroll
    for (int mf = 0; mf < 4; mf++) {
#pragma unroll
        for (int nf = 0; nf < 4; nf++) {
            int row = brow + warpM * 64 + mf * 16 + grp;
            int col = bcol + warpN * 32 + nf * 8 + qid * 2;
#pragma unroll
            for (int half = 0; half < 2; half++) {
                int r = row + half * 8;
                float c0 = acc[mf][nf][half * 2 + 0];
                float c1 = acc[mf][nf][half * 2 + 1];
                int sidx = col / DIMC;
                int rem = col - sidx * DIMC;
                int h = rem >> 6, d0 = rem & 63;
                int b = r >> 10, n = r & 1023;
                int bh = b * NHEAD + h;
                if (sidx == 0) {
                    size_t idx = ((size_t)bh * NS + n) * HDIM + d0;
                    *(float2*)&g_q[idx] = make_float2(c0 * SCALE_F, c1 * SCALE_F);
                } else if (sidx == 1) {
                    __nv_bfloat162 hv = __floats2bfloat162_rn(c0, c1);
                    __nv_bfloat162 lv = __floats2bfloat162_rn(
                        c0 - __bfloat162float(hv.x), c1 - __bfloat162float(hv.y));
                    size_t idx = ((size_t)bh * NS + n) * (HDIM / 2) + (d0 >> 1);
                    g_kbh[idx] = *(uint32_t*)&hv;
                    g_kbl[idx] = *(uint32_t*)&lv;
                } else {
                    size_t idx = ((size_t)bh * HDIM + d0) * NS + n;
                    g_vt[idx] = __uint_as_float(f2tf32(c0));
                    g_vt[idx + NS] = __uint_as_float(f2tf32(c1));
                }
            }
        }
    }
}

// ---------------------------------------------------------------------------
// proj GEMM (single tf32), 1 CTA/SM (NO reg cap — the R12 2-CTA cap spilled)
// ---------------------------------------------------------------------------
#define LDA 36
#define TILEF (128 * LDA)

__global__ __launch_bounds__(256) void proj_gemm(
    const float* __restrict__ Ahg, const float* __restrict__ Bhg,
    const float* __restrict__ bias, float* __restrict__ Cout)
{
    extern __shared__ float smf[];
    const uint32_t smb = smem_u32(smf);

    const int tid = threadIdx.x;
    const int warp = tid >> 5, lane = tid & 31;
    const int warpM = warp >> 2, warpN = warp & 3;
    const int grp = lane >> 2, qid = lane & 3;
    const int brow = blockIdx.y * 128;
    const int bcol = blockIdx.x * 128;

    size_t aoff[4], boff[4];
    uint32_t soff[4];
#pragma unroll
    for (int i = 0; i < 4; i++) {
        int ff = tid + 256 * i;
        int r = ff >> 3, kq = (ff & 7) << 2;
        aoff[i] = (size_t)(brow + r) * DIMC + kq;
        boff[i] = (size_t)(bcol + r) * DIMC + kq;
        soff[i] = (uint32_t)(r * LDA + kq) * 4u;
    }

    auto issue = [&](int s, int st) {
        const uint32_t base = smb + (uint32_t)(st * 2) * (TILEF * 4);
        const int k0 = s * 32;
#pragma unroll
        for (int i = 0; i < 4; i++) {
            cpa16(base + soff[i], Ahg + aoff[i] + k0);
            cpa16(base + TILEF * 4 + soff[i], Bhg + boff[i] + k0);
        }
        CPA_COMMIT();
    };

    float acc[4][4][4];
#pragma unroll
    for (int mf = 0; mf < 4; mf++)
#pragma unroll
        for (int nf = 0; nf < 4; nf++)
#pragma unroll
            for (int q = 0; q < 4; q++) acc[mf][nf][q] = 0.f;

    issue(0, 0);
    issue(1, 1);

    const int afr = (warpM * 64 + grp) * LDA + qid;
    const int bfr = (warpN * 32 + grp) * LDA + qid;

#pragma unroll 1
    for (int s = 0; s < 24; s++) {
        CPA_WAIT1();
        __syncthreads();
        const float* base = smf + (s & 1) * 2 * TILEF;
        const uint32_t* AhU = (const uint32_t*)(base + afr);
        const uint32_t* BhU = (const uint32_t*)(base + TILEF + bfr);

#pragma unroll
        for (int ks = 0; ks < 4; ks++) {
            const int ko = ks * 8;
            uint32_t bh0[4], bh1[4];
#pragma unroll
            for (int nf = 0; nf < 4; nf++) {
                bh0[nf] = BhU[nf * 8 * LDA + ko];
                bh1[nf] = BhU[nf * 8 * LDA + ko + 4];
            }
#pragma unroll
            for (int mf = 0; mf < 4; mf++) {
                const int ao = mf * 16 * LDA + ko;
                uint32_t ah0 = AhU[ao],     ah1 = AhU[ao + 8 * LDA];
                uint32_t ah2 = AhU[ao + 4], ah3 = AhU[ao + 8 * LDA + 4];
#pragma unroll
                for (int nf = 0; nf < 4; nf++)
                    mma1688(acc[mf][nf], ah0, ah1, ah2, ah3, bh0[nf], bh1[nf]);
            }
        }
        __syncthreads();
        if (s + 2 < 24) issue(s + 2, s & 1);
        else CPA_COMMIT();
    }

#pragma unroll
    for (int mf = 0; mf < 4; mf++) {
#pragma unroll
        for (int nf = 0; nf < 4; nf++) {
            int row = brow + warpM * 64 + mf * 16 + grp;
            int col = bcol + warpN * 32 + nf * 8 + qid * 2;
#pragma unroll
            for (int half = 0; half < 2; half++) {
                int r = row + half * 8;
                float2 bv = *(const float2*)&bias[col];
                *(float2*)&Cout[(size_t)r * DIMC + col] = make_float2(
                    acc[mf][nf][half * 2 + 0] + bv.x,
                    acc[mf][nf][half * 2 + 1] + bv.y);
            }
        }
    }
}

// ---------------------------------------------------------------------------
// Attention: S = Q K^T in 3xBF16, one-pass policy softmax, PV in tf32.
// 2 CTAs/SM (smem 2x104KB fits 228KB) for cross-CTA phase overlap.
// ---------------------------------------------------------------------------
#define KP 36                            // u32 pitch for K tiles
#define KTB (64 * KP * 4)                // 9216 B per K tile
#define VTB (64 * 68 * 4)                // 17408 B per V tile
#define OFF_KH 0
#define OFF_KL (2 * KTB)                 // 18432
#define OFF_VT (4 * KTB)                 // 36864
#define OFF_PS (4 * KTB + 2 * VTB)       // 71680
#define ATT_SMEM (OFF_PS + 128 * 68 * 4) // 106496 B
#define LDV 68
#define LDP 68

__global__ __launch_bounds__(256, 2) void attn_mma(const float* __restrict__ policy)
{
    extern __shared__ char sma[];
    const uint32_t smb = smem_u32(sma);
    float* PsF = (float*)(sma + OFF_PS);

    const int tid = threadIdx.x;
    const int warp = tid >> 5, lane = tid & 31;
    const int grp = lane >> 2, qid = lane & 3;
    const int bh = blockIdx.y;
    const int b = bh / NHEAD;
    const int h = bh - b * NHEAD;
    const int row0 = blockIdx.x * 128;

    const uint32_t* kbh = g_kbh + (size_t)bh * NS * (HDIM / 2);
    const uint32_t* kbl = g_kbl + (size_t)bh * NS * (HDIM / 2);
    const float* vtg = g_vt + (size_t)bh * HDIM * NS;
    const float* Qg  = g_q + (size_t)bh * NS * HDIM;
    const float* pol = policy + b * NS;

    const int lr = tid >> 2;            // 0..63
    const int lc4 = (tid & 3) << 2;

    auto issue = [&](int mt, int st) {
        const int m0 = mt * 64;
#pragma unroll
        for (int j = 0; j < 32; j += 16) {
            uint32_t doff = (uint32_t)(lr * KP + lc4 + j) * 4u;
            cpa16(smb + OFF_KH + st * KTB + doff, kbh + (size_t)(m0 + lr) * 32 + lc4 + j);
            cpa16(smb + OFF_KL + st * KTB + doff, kbl + (size_t)(m0 + lr) * 32 + lc4 + j);
        }
#pragma unroll
        for (int j = 0; j < 64; j += 16) {
            cpa16(smb + OFF_VT + st * VTB + (uint32_t)(lr * LDV + lc4 + j) * 4u,
                  vtg + (size_t)lr * NS + m0 + lc4 + j);
        }
        CPA_COMMIT();
    };

    issue(0, 0);
    issue(1, 1);

    // Q fragments: bf16 hi/lo, register-resident (4 k16 chunks)
    uint32_t qh[4][4], ql[4][4];
    {
        const float* Qw = Qg + (size_t)(row0 + warp * 16) * HDIM;
#pragma unroll
        for (int ck = 0; ck < 4; ck++) {
            int c0 = ck * 16 + 2 * qid;
            float x00 = Qw[grp * 64 + c0],       x01 = Qw[grp * 64 + c0 + 1];
            float x10 = Qw[(grp + 8) * 64 + c0], x11 = Qw[(grp + 8) * 64 + c0 + 1];
            float x20 = Qw[grp * 64 + c0 + 8],   x21 = Qw[grp * 64 + c0 + 9];
            float x30 = Qw[(grp + 8) * 64 + c0 + 8], x31 = Qw[(grp + 8) * 64 + c0 + 9];
            qh[ck][0] = pbf(x00, x01); ql[ck][0] = pbf(resbf(x00), resbf(x01));
            qh[ck][1] = pbf(x10, x11); ql[ck][1] = pbf(resbf(x10), resbf(x11));
            qh[ck][2] = pbf(x20, x21); ql[ck][2] = pbf(resbf(x20), resbf(x21));
            qh[ck][3] = pbf(x30, x31); ql[ck][3] = pbf(resbf(x30), resbf(x31));
        }
    }

    float accO[8][4];
#pragma unroll
    for (int nf = 0; nf < 8; nf++)
#pragma unroll
        for (int q = 0; q < 4; q++) accO[nf][q] = 0.f;
    float l0 = 0.f, l1 = 0.f;
    const int rg0 = row0 + warp * 16 + grp;
    const int rg1 = rg0 + 8;

#pragma unroll 1
    for (int mt = 0; mt < 16; mt++) {
        const int m0 = mt * 64;
        const int st = mt & 1;
        CPA_WAIT1();
        __syncthreads();

        const uint32_t* KhU = (const uint32_t*)(sma + OFF_KH + st * KTB);
        const uint32_t* KlU = (const uint32_t*)(sma + OFF_KL + st * KTB);
        const uint32_t* VtU = (const uint32_t*)(sma + OFF_VT + st * VTB);
        const uint32_t* PsU = (const uint32_t*)PsF;

        // S = Q K^T (3xBF16)
        float c[8][4];
#pragma unroll
        for (int nf = 0; nf < 8; nf++)
#pragma unroll
            for (int q = 0; q < 4; q++) c[nf][q] = 0.f;
#pragma unroll
        for (int ck = 0; ck < 4; ck++) {
#pragma unroll
            for (int nf = 0; nf < 8; nf++) {
                int rb = (nf * 8 + grp) * KP + ck * 8 + qid;
                uint32_t b0 = KhU[rb], b1 = KhU[rb + 4];
                uint32_t l0r = KlU[rb], l1r = KlU[rb + 4];
                mmabf(c[nf], qh[ck], b0, b1);
                mmabf(c[nf], qh[ck], l0r, l1r);
                mmabf(c[nf], ql[ck], b0, b1);
            }
        }

        // one-pass softmax (no shift); P truncated to tf32; l from truncated P
        float tl0 = 0.f, tl1 = 0.f;
        float* Pw0 = PsF + (warp * 16 + grp) * LDP + 2 * qid;
        float* Pw1 = Pw0 + 8 * LDP;
#pragma unroll
        for (int nf = 0; nf < 8; nf++) {
            int mg = m0 + nf * 8 + 2 * qid;
            float2 pp = *(const float2*)&pol[mg];
            float w00 = (mg == rg0) ? 1.f : pp.x;
            float w01 = (mg + 1 == rg0) ? 1.f : pp.y;
            float w10 = (mg == rg1) ? 1.f : pp.x;
            float w11 = (mg + 1 == rg1) ? 1.f : pp.y;
            float e00 = __expf(c[nf][0]) * w00;
            float e01 = __expf(c[nf][1]) * w01;
            float e10 = __expf(c[nf][2]) * w10;
            float e11 = __expf(c[nf][3]) * w11;
            float t00 = __uint_as_float(__float_as_uint(e00) & 0xFFFFE000u);
            float t01 = __uint_as_float(__float_as_uint(e01) & 0xFFFFE000u);
            float t10 = __uint_as_float(__float_as_uint(e10) & 0xFFFFE000u);
            float t11 = __uint_as_float(__float_as_uint(e11) & 0xFFFFE000u);
            tl0 += t00 + t01;
            tl1 += t10 + t11;
            *(float2*)&Pw0[nf * 8] = make_float2(t00, t01);
            *(float2*)&Pw1[nf * 8] = make_float2(t10, t11);
        }
        tl0 += __shfl_xor_sync(0xffffffffu, tl0, 1);
        tl0 += __shfl_xor_sync(0xffffffffu, tl0, 2);
        tl1 += __shfl_xor_sync(0xffffffffu, tl1, 1);
        tl1 += __shfl_xor_sync(0xffffffffu, tl1, 2);
        l0 += tl0;
        l1 += tl1;
        __syncwarp();

        // O += P V (tf32)
#pragma unroll
        for (int ks = 0; ks < 8; ks++) {
            const int ko = ks * 8;
            int pb = (warp * 16 + grp) * LDP + ko + qid;
            uint32_t a0 = PsU[pb], a1 = PsU[pb + 8 * LDP];
            uint32_t a2 = PsU[pb + 4], a3 = PsU[pb + 8 * LDP + 4];
#pragma unroll
            for (int nf = 0; nf < 8; nf++) {
                int vb = (nf * 8 + grp) * LDV + ko + qid;
                mma1688(accO[nf], a0, a1, a2, a3, VtU[vb], VtU[vb + 4]);
            }
        }
        __syncthreads();
        if (mt + 2 < 16) issue(mt + 2, st);
        else CPA_COMMIT();
    }

    // epilogue: normalize, tf32-round (proj A-stream), write g_ao
    float inv0 = 1.0f / (l0 + EPS_F);
    float inv1 = 1.0f / (l1 + EPS_F);
#pragma unroll
    for (int nf = 0; nf < 8; nf++) {
        int d = nf * 8 + 2 * qid;
        size_t b0a = ((size_t)(b * NS + rg0)) * DIMC + h * HDIM + d;
        size_t b1a = ((size_t)(b * NS + rg1)) * DIMC + h * HDIM + d;
        *(float2*)&g_ao[b0a] = make_float2(
            __uint_as_float(f2tf32(accO[nf][0] * inv0)),
            __uint_as_float(f2tf32(accO[nf][1] * inv0)));
        *(float2*)&g_ao[b1a] = make_float2(
            __uint_as_float(f2tf32(accO[nf][2] * inv1)),
            __uint_as_float(f2tf32(accO[nf][3] * inv1)));
    }
}

extern "C" void kernel_launch(void* const* d_in, const int* in_sizes, int n_in,
                              void* d_out, int out_size)
{
    const float* x      = (const float*)d_in[0];
    const float* policy = (const float*)d_in[1];
    const float* qkv_w  = (const float*)d_in[2];
    const float* proj_w = (const float*)d_in[3];
    const float* proj_b = (const float*)d_in[4];
    float* out = (float*)d_out;

    const int SMEMQ = 2 * 4 * QTILE * 4;  // 81920 B
    const int SMEMP = 2 * 2 * TILEF * 4;  // 73728 B
    static bool attr_done = false;
    if (!attr_done) {
        cudaFuncSetAttribute(gemm_qkv, cudaFuncAttributeMaxDynamicSharedMemorySize, SMEMQ);
        cudaFuncSetAttribute(proj_gemm, cudaFuncAttributeMaxDynamicSharedMemorySize, SMEMP);
        cudaFuncSetAttribute(attn_mma, cudaFuncAttributeMaxDynamicSharedMemorySize, ATT_SMEM);
        attr_done = true;
    }

    uint32_t *xbh, *xbl, *wbh, *wbl;
    float *pw, *ao;
    cudaGetSymbolAddress((void**)&xbh, g_xbh);
    cudaGetSymbolAddress((void**)&xbl, g_xbl);
    cudaGetSymbolAddress((void**)&wbh, g_wbh);
    cudaGetSymbolAddress((void**)&wbl, g_wbl);
    cudaGetSymbolAddress((void**)&pw, g_pw);
    cudaGetSymbolAddress((void**)&ao, g_ao);

    // 0) splits
    split_bf16<<<(NB * NS * DIMC / 4 + 255) / 256, 256>>>(
        (const float4*)x, xbh, xbl, NB * NS * DIMC / 4);
    split_bf16<<<(3 * DIMC * DIMC / 4 + 255) / 256, 256>>>(
        (const float4*)qkv_w, wbh, wbl, 3 * DIMC * DIMC / 4);
    split_tf32<<<(DIMC * DIMC / 4 + 255) / 256, 256>>>(
        (const float4*)proj_w, (float4*)pw, DIMC * DIMC / 4);

    // 1) QKV (3xBF16) -> q / k(bf16 hi-lo) / v(transposed tf32)
    gemm_qkv<<<dim3(2304 / 128, 8192 / 128), 256, SMEMQ>>>(xbh, xbl, wbh, wbl);
    // 2) attention (bf16 S, tf32 PV, one-pass policy softmax), 2 CTAs/SM
    attn_mma<<<dim3(NS / 128, NB * NHEAD), 256, ATT_SMEM>>>(policy);
    // 3) proj (single tf32) + bias, 1 CTA/SM
    proj_gemm<<<dim3(DIMC / 128, 8192 / 128), 256, SMEMP>>>(ao, pw, proj_b, out);
}